// round 2
// baseline (speedup 1.0000x reference)
#include <cuda_runtime.h>

// Problem: CtcBoundaryLossV3
// Inputs (metadata order):
//   d_in[0] alpha          float32  [B, T]
//   d_in[1] ctc_log_probs  float32  [B, T, V]
//   d_in[2] mask           float32  [B, T]
//   d_in[3] text_length    int32    [B]   (jax int64 silently -> int32 without x64)
// Output: float32 scalar.

#define SPLIT 8
#define MAXB  128

// log(3.0)
#define LOG_THR 1.0986122886681098f

__device__ float g_psum[MAXB * SPLIT];
__device__ int   g_pcnt[MAXB * SPLIT];

// Kernel 1: per-(batch, chunk) partial reductions.
// grid = (SPLIT, B), block = 256 threads. Each block handles chunkLen frames.
__global__ void ctc_partial_kernel(const float* __restrict__ alpha,
                                   const float* __restrict__ ctc,
                                   const float* __restrict__ mask,
                                   int T, int V, int chunkLen) {
    const int chunk = blockIdx.x;
    const int b     = blockIdx.y;
    const int t0    = chunk * chunkLen;
    const int tEnd  = min(t0 + chunkLen, T);

    float lsum = 0.0f;
    int   lcnt = 0;

    const size_t rowBase = (size_t)b * (size_t)T;

    for (int t = t0 + threadIdx.x; t < tEnd; t += blockDim.x) {
        const size_t idx = rowBase + (size_t)t;
        float a  = alpha[idx];
        float mk = mask[idx];
        float bl = ctc[idx * (size_t)V];   // blank column (index 0)
        lsum += a;
        bool trig = (1.0f - bl) > LOG_THR;
        lcnt += (trig && (mk != 0.0f)) ? 1 : 0;
    }

    // warp reduce
    #pragma unroll
    for (int off = 16; off > 0; off >>= 1) {
        lsum += __shfl_down_sync(0xFFFFFFFFu, lsum, off);
        lcnt += __shfl_down_sync(0xFFFFFFFFu, lcnt, off);
    }

    __shared__ float s_sum[8];
    __shared__ int   s_cnt[8];
    const int wid = threadIdx.x >> 5;
    const int lid = threadIdx.x & 31;
    if (lid == 0) { s_sum[wid] = lsum; s_cnt[wid] = lcnt; }
    __syncthreads();

    if (threadIdx.x == 0) {
        float tsum = 0.0f;
        int   tcnt = 0;
        const int nw = (blockDim.x + 31) >> 5;
        #pragma unroll
        for (int w = 0; w < 8; w++) {
            if (w < nw) { tsum += s_sum[w]; tcnt += s_cnt[w]; }
        }
        g_psum[b * SPLIT + chunk] = tsum;
        g_pcnt[b * SPLIT + chunk] = tcnt;
    }
}

// Kernel 2: combine partials, compute L, closed-form per-sample loss, mean.
// 1 block, MAXB threads.
__global__ void ctc_finalize_kernel(const int* __restrict__ text_length,
                                    float* __restrict__ out, int B) {
    __shared__ float s_rs[MAXB];
    __shared__ int   s_ns[MAXB];
    __shared__ float s_ps[MAXB];
    __shared__ int   sL;

    const int b = threadIdx.x;

    if (b < B) {
        float rs = 0.0f;
        int   ns = 0;
        #pragma unroll
        for (int c = 0; c < SPLIT; c++) {
            rs += g_psum[b * SPLIT + c];
            ns += g_pcnt[b * SPLIT + c];
        }
        s_rs[b] = rs;
        s_ns[b] = ns;
    }
    __syncthreads();

    if (threadIdx.x == 0) {
        int maxLen = 0, maxText = 0;
        for (int i = 0; i < B; i++) {
            int li = (s_ns[i] >= 1) ? s_ns[i] : 1;
            if (li > maxLen) maxLen = li;
            int tl = text_length[i];
            if (tl > maxText) maxText = tl;
        }
        sL = (maxLen < maxText) ? maxLen : maxText;
    }
    __syncthreads();

    if (b < B) {
        const int L  = sL;
        int tl = text_length[b];
        int m  = min(tl, L);        // m >= 1 always (tl >= 1, L >= 1)
        float ps;
        if (s_ns[b] >= 1) {
            int k = min(s_ns[b], m);
            ps = (float)k * fabsf(s_rs[b] - 1.0f) + (float)(m - k);
        } else {
            ps = (float)(m - 1);
        }
        s_ps[b] = ps;
    }
    __syncthreads();

    if (threadIdx.x == 0) {
        float tot = 0.0f;
        for (int i = 0; i < B; i++) tot += s_ps[i];
        out[0] = tot / (float)B;
    }
}

extern "C" void kernel_launch(void* const* d_in, const int* in_sizes, int n_in,
                              void* d_out, int out_size) {
    const float* alpha = (const float*)d_in[0];
    const float* ctc   = (const float*)d_in[1];
    const float* mask  = (const float*)d_in[2];
    const int*   tlen  = (const int*)d_in[3];
    float*       out   = (float*)d_out;

    const int B  = in_sizes[3];
    const int BT = in_sizes[0];
    const int T  = BT / B;
    const int V  = in_sizes[1] / BT;
    const int chunkLen = (T + SPLIT - 1) / SPLIT;

    dim3 grid(SPLIT, B);
    ctc_partial_kernel<<<grid, 256>>>(alpha, ctc, mask, T, V, chunkLen);
    ctc_finalize_kernel<<<1, MAXB>>>(tlen, out, B);
}